// round 1
// baseline (speedup 1.0000x reference)
#include <cuda_runtime.h>
#include <math.h>

#define B_SI 4.1491f
#define B_O  5.803f
#define CUTOFF 3.5f
#define PI_F 3.14159265358979323846f

#define MAXN 16384
#define MAXB 1024

#define IPB 16   // atoms i per block in hist kernel
#define LPI 16   // j-lanes per atom

__device__ float4 g_pos[MAXN];     // x, y, z, b (scattering length)
__device__ float  g_hist[MAXB];
__device__ float  g_sumq;
__device__ float  g_sumvf;

// ---------------------------------------------------------------------------
// helpers
// ---------------------------------------------------------------------------
__device__ __forceinline__ void load_cell_inv(const float* __restrict__ cell,
                                              float c[9], float inv[9]) {
#pragma unroll
    for (int k = 0; k < 9; k++) c[k] = cell[k];
    float a00=c[0],a01=c[1],a02=c[2],a10=c[3],a11=c[4],a12=c[5],a20=c[6],a21=c[7],a22=c[8];
    float det = a00*(a11*a22 - a12*a21) - a01*(a10*a22 - a12*a20) + a02*(a10*a21 - a11*a20);
    float id = 1.0f / det;
    inv[0]=(a11*a22-a12*a21)*id; inv[1]=(a02*a21-a01*a22)*id; inv[2]=(a01*a12-a02*a11)*id;
    inv[3]=(a12*a20-a10*a22)*id; inv[4]=(a00*a22-a02*a20)*id; inv[5]=(a02*a10-a00*a12)*id;
    inv[6]=(a10*a21-a11*a20)*id; inv[7]=(a01*a20-a00*a21)*id; inv[8]=(a00*a11-a01*a10)*id;
}

// minimum-image displacement under general periodic cell
// frac = disp @ inv(cell); frac -= round(frac); disp = frac @ cell
__device__ __forceinline__ float3 min_image(float dx, float dy, float dz,
                                            const float c[9], const float inv[9]) {
    float fx = dx*inv[0] + dy*inv[3] + dz*inv[6];
    float fy = dx*inv[1] + dy*inv[4] + dz*inv[7];
    float fz = dx*inv[2] + dy*inv[5] + dz*inv[8];
    fx -= rintf(fx); fy -= rintf(fy); fz -= rintf(fz);
    float ox = fx*c[0] + fy*c[3] + fz*c[6];
    float oy = fx*c[1] + fy*c[4] + fz*c[7];
    float oz = fx*c[2] + fy*c[5] + fz*c[8];
    return make_float3(ox, oy, oz);
}

// ---------------------------------------------------------------------------
// kernel 0: pack positions + scattering lengths, zero scratch
// ---------------------------------------------------------------------------
__global__ void k_prep(const float* __restrict__ pos, const int* __restrict__ species,
                       int N, int nbins) {
    int i = blockIdx.x * blockDim.x + threadIdx.x;
    if (i < N) {
        float b = (species[i] == 0) ? B_SI : B_O;
        g_pos[i] = make_float4(pos[3*i+0], pos[3*i+1], pos[3*i+2], b);
    }
    if (i < nbins) g_hist[i] = 0.0f;
    if (i == 0) { g_sumq = 0.0f; g_sumvf = 0.0f; }
}

// ---------------------------------------------------------------------------
// kernel 1: weighted pair histogram (CIC binning) via shared-mem atomics
// ---------------------------------------------------------------------------
__global__ void k_hist(const float* __restrict__ cell, const float* __restrict__ rbins,
                       int N, int nbins) {
    __shared__ float sh[MAXB];
    int tid = threadIdx.x;
    for (int k = tid; k < nbins; k += blockDim.x) sh[k] = 0.0f;

    float c[9], inv[9];
    load_cell_inv(cell, c, inv);
    float r0 = rbins[0];
    float dr = rbins[1] - r0;
    float rmax  = r0 + dr * (float)(nbins - 1);
    float rmax2 = rmax * rmax;
    __syncthreads();

    int i    = blockIdx.x * IPB + tid / LPI;
    int lane = tid % LPI;
    if (i < N) {
        float4 p = g_pos[i];
        for (int j = lane; j < N; j += LPI) {
            if (j == i) continue;
            float4 q = g_pos[j];
            float3 d = min_image(p.x - q.x, p.y - q.y, p.z - q.z, c, inv);
            float d2 = d.x*d.x + d.y*d.y + d.z*d.z;
            if (d2 < rmax2) {
                float dist = sqrtf(d2);
                float x  = (dist - r0) / dr;
                float fi = floorf(x);
                int  i0  = (int)fi;
                if (i0 >= 0 && i0 < nbins - 1) {
                    float f = x - fi;
                    float w = p.w * q.w;
                    atomicAdd(&sh[i0],     w * (1.0f - f));
                    atomicAdd(&sh[i0 + 1], w * f);
                }
            }
        }
    }
    __syncthreads();
    for (int k = tid; k < nbins; k += blockDim.x)
        if (sh[k] != 0.0f) atomicAdd(&g_hist[k], sh[k]);
}

// ---------------------------------------------------------------------------
// kernel 2: tetrahedral order parameter. One block per atom (Si centers only).
// Per-thread sorted top-4 by d^2 over O neighbours, warp shuffle merge,
// final merge + q_i by thread 0.
// ---------------------------------------------------------------------------
__global__ void k_tet(const float* __restrict__ cell, const int* __restrict__ species,
                      int N) {
    int i = blockIdx.x;
    if (species[i] != 0) return;   // uniform exit for whole block

    int tid = threadIdx.x;
    float c[9], inv[9];
    load_cell_inv(cell, c, inv);
    float4 p = g_pos[i];

    float bd[4] = {1e12f, 1e12f, 1e12f, 1e12f};   // d^2, ascending
    int   bj[4] = {-1, -1, -1, -1};

    for (int j = tid; j < N; j += blockDim.x) {
        if (j == i) continue;
        if (species[j] == 0) continue;            // only O neighbours
        float4 q = g_pos[j];
        float3 d = min_image(p.x - q.x, p.y - q.y, p.z - q.z, c, inv);
        float d2 = d.x*d.x + d.y*d.y + d.z*d.z;
        if (d2 < bd[3]) {
            int k = 3;
#pragma unroll
            for (int t = 0; t < 3; t++) {
                if (k > 0 && bd[k-1] > d2) { bd[k] = bd[k-1]; bj[k] = bj[k-1]; k--; }
            }
            bd[k] = d2; bj[k] = j;
        }
    }

    // warp-level merge of sorted 4-lists
    const unsigned mask = 0xffffffffu;
#pragma unroll
    for (int off = 16; off > 0; off >>= 1) {
        float od[4]; int oj[4];
#pragma unroll
        for (int k = 0; k < 4; k++) {
            od[k] = __shfl_down_sync(mask, bd[k], off);
            oj[k] = __shfl_down_sync(mask, bj[k], off);
        }
        float nd[4]; int nj[4];
        int a = 0, b = 0;
#pragma unroll
        for (int k = 0; k < 4; k++) {
            bool takeA = (b >= 4) || (a < 4 && bd[a] <= od[b]);
            if (takeA) { nd[k] = bd[a]; nj[k] = bj[a]; a++; }
            else       { nd[k] = od[b]; nj[k] = oj[b]; b++; }
        }
#pragma unroll
        for (int k = 0; k < 4; k++) { bd[k] = nd[k]; bj[k] = nj[k]; }
    }

    __shared__ float sd[16];
    __shared__ int   sj[16];
    int wid = tid >> 5, lid = tid & 31;
    if (lid == 0) {
#pragma unroll
        for (int k = 0; k < 4; k++) { sd[wid*4 + k] = bd[k]; sj[wid*4 + k] = bj[k]; }
    }
    __syncthreads();

    if (tid == 0) {
        float fd[4] = {1e12f, 1e12f, 1e12f, 1e12f};
        int   fj[4] = {-1, -1, -1, -1};
        int nw = (blockDim.x + 31) / 32;
        for (int m = 0; m < nw * 4; m++) {
            float d2 = sd[m];
            if (d2 < fd[3]) {
                int k = 3;
                while (k > 0 && fd[k-1] > d2) { fd[k] = fd[k-1]; fj[k] = fj[k-1]; k--; }
                fd[k] = d2; fj[k] = sj[m];
            }
        }
        float d3 = sqrtf(fd[3]);
        if (d3 < CUTOFF) {
            float ux[4], uy[4], uz[4];
#pragma unroll
            for (int k = 0; k < 4; k++) {
                float4 q = g_pos[fj[k]];
                float3 d = min_image(p.x - q.x, p.y - q.y, p.z - q.z, c, inv);
                float dk = sqrtf(fd[k]);
                ux[k] = d.x / dk; uy[k] = d.y / dk; uz[k] = d.z / dk;
            }
            float s = 0.0f;
#pragma unroll
            for (int k = 0; k < 4; k++)
#pragma unroll
                for (int l = k + 1; l < 4; l++) {
                    float cv = ux[k]*ux[l] + uy[k]*uy[l] + uz[k]*uz[l];
                    float t = cv + (1.0f / 3.0f);
                    s += t * t;
                }
            float qi = 1.0f - 0.375f * s;
            atomicAdd(&g_sumq, qi);
            atomicAdd(&g_sumvf, 1.0f);
        }
    }
}

// ---------------------------------------------------------------------------
// kernel 3: finalize — mean b, G(r), T(r), S(Q), q_tet. Single block.
// ---------------------------------------------------------------------------
__global__ void k_final(const float* __restrict__ cell, const float* __restrict__ rbins,
                        const float* __restrict__ qbins, const int* __restrict__ species,
                        int N, int nbins, int nq, float* __restrict__ out) {
    __shared__ float shGr[MAXB];
    __shared__ float red[512];
    int tid = threadIdx.x;

    // mean scattering length
    float lb = 0.0f;
    for (int j = tid; j < N; j += blockDim.x)
        lb += (species[j] == 0) ? B_SI : B_O;
    red[tid] = lb;
    __syncthreads();
    for (int s = blockDim.x / 2; s > 0; s >>= 1) {
        if (tid < s) red[tid] += red[tid + s];
        __syncthreads();
    }
    float meanb = red[0] / (float)N;

    // cell volume / density
    float c0=cell[0],c1=cell[1],c2=cell[2],c3=cell[3],c4=cell[4],c5=cell[5],c6=cell[6],c7=cell[7],c8=cell[8];
    float det = c0*(c4*c8 - c5*c7) - c1*(c3*c8 - c5*c6) + c2*(c3*c7 - c4*c6);
    float V   = fabsf(det);
    float rho = (float)N / V;

    float r0 = rbins[0];
    float dr = rbins[1] - r0;
    float wnorm = 1.0f / (meanb * meanb);

    for (int k = tid; k < nbins; k += blockDim.x) {
        float r = rbins[k];
        float shell = 4.0f * PI_F * r * r * dr;
        float Gr = (g_hist[k] * wnorm) / ((float)N * rho * shell);
        shGr[k] = Gr;
        out[k] = Gr;                                  // G_r
        out[nbins + k] = 4.0f * PI_F * rho * r * Gr;  // T_r
    }
    __syncthreads();

    for (int iq = tid; iq < nq; iq += blockDim.x) {
        float Q = qbins[iq];
        float s = 0.0f;
        for (int k = 0; k < nbins; k++) {
            float r  = rbins[k];
            float qr = Q * r;
            float sc = (qr != 0.0f) ? (sinf(qr) / qr) : 1.0f;
            s += r * r * (shGr[k] - 1.0f) * sc;
        }
        out[2 * nbins + iq] = 1.0f + 4.0f * PI_F * rho * dr * s;   // S_Q
    }

    if (tid == 0)
        out[2 * nbins + nq] = g_sumq / fmaxf(g_sumvf, 1.0f);       // q_tet
}

// ---------------------------------------------------------------------------
// launch
// ---------------------------------------------------------------------------
extern "C" void kernel_launch(void* const* d_in, const int* in_sizes, int n_in,
                              void* d_out, int out_size) {
    const float* pos     = (const float*)d_in[0];
    const float* cell    = (const float*)d_in[1];
    const float* rbins   = (const float*)d_in[2];
    const float* qbins   = (const float*)d_in[3];
    const int*   species = (const int*)d_in[4];

    int N     = in_sizes[0] / 3;
    int nbins = in_sizes[2];
    int nq    = in_sizes[3];
    float* out = (float*)d_out;

    int mx = (N > nbins) ? N : nbins;
    k_prep<<<(mx + 255) / 256, 256>>>(pos, species, N, nbins);

    int histBlocks = (N + IPB - 1) / IPB;
    k_hist<<<histBlocks, IPB * LPI>>>(cell, rbins, N, nbins);

    k_tet<<<N, 128>>>(cell, species, N);

    k_final<<<1, 512>>>(cell, rbins, qbins, species, N, nbins, nq, out);
}

// round 4
// speedup vs baseline: 1.4504x; 1.4504x over previous
#include <cuda_runtime.h>
#include <math.h>

#define B_SI 4.1491f
#define B_O  5.803f
#define CUTOFF 3.5f
#define PI_F 3.14159265358979323846f

#define MAXN 16384
#define MAXB 1024

#define IPB 8    // atom slots per block in hist kernel (each covers i and N-1-i)
#define LPI 32   // j-lanes per atom slot

__device__ float4 g_pos[MAXN];       // x, y, z, b (scattering length; b<5 => Si)
__device__ float  g_hist[MAXB];
__device__ float  g_integrand[MAXB]; // r^2 (G_r - 1)
__device__ float  g_sumq;
__device__ int    g_cntvf;
__device__ int    g_nsi;

// ---------------------------------------------------------------------------
// helpers
// ---------------------------------------------------------------------------
__device__ __forceinline__ void load_cell_inv(const float* __restrict__ cell,
                                              float c[9], float inv[9]) {
#pragma unroll
    for (int k = 0; k < 9; k++) c[k] = cell[k];
    float a00=c[0],a01=c[1],a02=c[2],a10=c[3],a11=c[4],a12=c[5],a20=c[6],a21=c[7],a22=c[8];
    float det = a00*(a11*a22 - a12*a21) - a01*(a10*a22 - a12*a20) + a02*(a10*a21 - a11*a20);
    float id = 1.0f / det;
    inv[0]=(a11*a22-a12*a21)*id; inv[1]=(a02*a21-a01*a22)*id; inv[2]=(a01*a12-a02*a11)*id;
    inv[3]=(a12*a20-a10*a22)*id; inv[4]=(a00*a22-a02*a20)*id; inv[5]=(a02*a10-a00*a12)*id;
    inv[6]=(a10*a21-a11*a20)*id; inv[7]=(a01*a20-a00*a21)*id; inv[8]=(a00*a11-a01*a10)*id;
}

__device__ __forceinline__ bool cell_is_diag(const float c[9]) {
    return c[1]==0.0f && c[2]==0.0f && c[3]==0.0f &&
           c[5]==0.0f && c[6]==0.0f && c[7]==0.0f;
}

// general minimum-image
__device__ __forceinline__ float3 min_image(float dx, float dy, float dz,
                                            const float c[9], const float inv[9]) {
    float fx = dx*inv[0] + dy*inv[3] + dz*inv[6];
    float fy = dx*inv[1] + dy*inv[4] + dz*inv[7];
    float fz = dx*inv[2] + dy*inv[5] + dz*inv[8];
    fx -= rintf(fx); fy -= rintf(fy); fz -= rintf(fz);
    float ox = fx*c[0] + fy*c[3] + fz*c[6];
    float oy = fx*c[1] + fy*c[4] + fz*c[7];
    float oz = fx*c[2] + fy*c[5] + fz*c[8];
    return make_float3(ox, oy, oz);
}

// diagonal-cell minimum-image (matches general path arithmetic for diag cell)
__device__ __forceinline__ float3 min_image_diag(float dx, float dy, float dz,
                                                 float Lx, float Ly, float Lz,
                                                 float iLx, float iLy, float iLz) {
    float fx = dx * iLx, fy = dy * iLy, fz = dz * iLz;
    fx -= rintf(fx); fy -= rintf(fy); fz -= rintf(fz);
    return make_float3(fx * Lx, fy * Ly, fz * Lz);
}

// ---------------------------------------------------------------------------
// kernel 0: pack positions + scattering lengths, zero scratch, count Si
// ---------------------------------------------------------------------------
__global__ void k_prep(const float* __restrict__ pos, const int* __restrict__ species,
                       int N, int nbins) {
    int i = blockIdx.x * blockDim.x + threadIdx.x;
    if (i < N) {
        int isSi = (species[i] == 0);
        float b = isSi ? B_SI : B_O;
        g_pos[i] = make_float4(pos[3*i+0], pos[3*i+1], pos[3*i+2], b);
        if (isSi) atomicAdd(&g_nsi, 1);
    }
    if (i < nbins) g_hist[i] = 0.0f;
    if (i == 0) { g_sumq = 0.0f; g_cntvf = 0; }
}
__global__ void k_zero() { g_nsi = 0; }

// ---------------------------------------------------------------------------
// kernel 1: weighted pair histogram, i<j symmetry (doubled), CIC binning
// Slot s of block b handles i = b*IPB+s (i < N/2) AND its mirror N-1-i, so
// every slot does exactly N-1 inner iterations (balanced).
// ---------------------------------------------------------------------------
__global__ void k_hist(const float* __restrict__ cell, const float* __restrict__ rbins,
                       int N, int nbins) {
    __shared__ float sh[MAXB];
    int tid = threadIdx.x;
    for (int k = tid; k < nbins; k += blockDim.x) sh[k] = 0.0f;

    float c[9], inv[9];
    load_cell_inv(cell, c, inv);
    bool diag = cell_is_diag(c);
    float Lx=c[0], Ly=c[4], Lz=c[8];
    float iLx=1.0f/Lx, iLy=1.0f/Ly, iLz=1.0f/Lz;

    float r0 = rbins[0];
    float dr = rbins[1] - r0;
    float idr = 1.0f / dr;
    float rmax  = r0 + dr * (float)(nbins - 1);
    float rmax2 = rmax * rmax;
    __syncthreads();

    int slot = tid / LPI;
    int lane = tid % LPI;
    int half = N / 2;

#pragma unroll 1
    for (int pass = 0; pass < 2; pass++) {
        int i = blockIdx.x * IPB + slot;
        if (i >= half) break;
        if (pass == 1) i = N - 1 - i;
        float4 p = g_pos[i];
        if (diag) {
            for (int j = i + 1 + lane; j < N; j += LPI) {
                float4 q = g_pos[j];
                float3 d = min_image_diag(p.x-q.x, p.y-q.y, p.z-q.z, Lx,Ly,Lz, iLx,iLy,iLz);
                float d2 = d.x*d.x + d.y*d.y + d.z*d.z;
                if (d2 < rmax2) {
                    float dist = sqrtf(d2);
                    float x  = (dist - r0) * idr;
                    float fi = floorf(x);
                    int  i0  = (int)fi;
                    if (i0 >= 0 && i0 < nbins - 1) {
                        float f = x - fi;
                        float w = p.w * q.w;
                        atomicAdd(&sh[i0],     w * (1.0f - f));
                        atomicAdd(&sh[i0 + 1], w * f);
                    }
                }
            }
        } else {
            for (int j = i + 1 + lane; j < N; j += LPI) {
                float4 q = g_pos[j];
                float3 d = min_image(p.x-q.x, p.y-q.y, p.z-q.z, c, inv);
                float d2 = d.x*d.x + d.y*d.y + d.z*d.z;
                if (d2 < rmax2) {
                    float dist = sqrtf(d2);
                    float x  = (dist - r0) * idr;
                    float fi = floorf(x);
                    int  i0  = (int)fi;
                    if (i0 >= 0 && i0 < nbins - 1) {
                        float f = x - fi;
                        float w = p.w * q.w;
                        atomicAdd(&sh[i0],     w * (1.0f - f));
                        atomicAdd(&sh[i0 + 1], w * f);
                    }
                }
            }
        }
    }
    __syncthreads();
    for (int k = tid; k < nbins; k += blockDim.x)
        if (sh[k] != 0.0f) atomicAdd(&g_hist[k], 2.0f * sh[k]);   // unordered -> ordered
}

// ---------------------------------------------------------------------------
// kernel 2: tetrahedral order parameter. One WARP per center atom.
// Si centers only (pos.w < 5 => Si). Neighbours must be O (pos.w > 5), which
// also excludes j == i automatically.
// ---------------------------------------------------------------------------
#define TET_WARPS 8
__global__ void k_tet(const float* __restrict__ cell, int N) {
    int wid  = threadIdx.x >> 5;
    int lane = threadIdx.x & 31;
    int i = blockIdx.x * TET_WARPS + wid;
    if (i >= N) return;

    float4 p = g_pos[i];
    if (p.w > 5.0f) return;   // not Si; uniform per warp

    float c[9], inv[9];
    load_cell_inv(cell, c, inv);
    bool diag = cell_is_diag(c);
    float Lx=c[0], Ly=c[4], Lz=c[8];
    float iLx=1.0f/Lx, iLy=1.0f/Ly, iLz=1.0f/Lz;

    float bd[4] = {1e12f, 1e12f, 1e12f, 1e12f};   // d^2, ascending
    int   bj[4] = {-1, -1, -1, -1};

    for (int j = lane; j < N; j += 32) {
        float4 q = g_pos[j];
        if (q.w < 5.0f) continue;                 // only O neighbours
        float3 d = diag ? min_image_diag(p.x-q.x, p.y-q.y, p.z-q.z, Lx,Ly,Lz, iLx,iLy,iLz)
                        : min_image(p.x-q.x, p.y-q.y, p.z-q.z, c, inv);
        float d2 = d.x*d.x + d.y*d.y + d.z*d.z;
        if (d2 < bd[3]) {
            int k = 3;
#pragma unroll
            for (int t = 0; t < 3; t++) {
                if (k > 0 && bd[k-1] > d2) { bd[k] = bd[k-1]; bj[k] = bj[k-1]; k--; }
            }
            bd[k] = d2; bj[k] = j;
        }
    }

    // warp merge of sorted 4-lists
    const unsigned mask = 0xffffffffu;
#pragma unroll
    for (int off = 16; off > 0; off >>= 1) {
        float od[4]; int oj[4];
#pragma unroll
        for (int k = 0; k < 4; k++) {
            od[k] = __shfl_down_sync(mask, bd[k], off);
            oj[k] = __shfl_down_sync(mask, bj[k], off);
        }
        float nd[4]; int nj[4];
        int a = 0, b = 0;
#pragma unroll
        for (int k = 0; k < 4; k++) {
            bool takeA = (b >= 4) || (a < 4 && bd[a] <= od[b]);
            if (takeA) { nd[k] = bd[a]; nj[k] = bj[a]; a++; }
            else       { nd[k] = od[b]; nj[k] = oj[b]; b++; }
        }
#pragma unroll
        for (int k = 0; k < 4; k++) { bd[k] = nd[k]; bj[k] = nj[k]; }
    }

    if (lane == 0) {
        float d3 = sqrtf(bd[3]);
        if (d3 < CUTOFF) {
            float ux[4], uy[4], uz[4];
#pragma unroll
            for (int k = 0; k < 4; k++) {
                float4 q = g_pos[bj[k]];
                float3 d = diag ? min_image_diag(p.x-q.x, p.y-q.y, p.z-q.z, Lx,Ly,Lz, iLx,iLy,iLz)
                                : min_image(p.x-q.x, p.y-q.y, p.z-q.z, c, inv);
                float dk = sqrtf(bd[k]);
                ux[k] = d.x / dk; uy[k] = d.y / dk; uz[k] = d.z / dk;
            }
            float s = 0.0f;
#pragma unroll
            for (int k = 0; k < 4; k++)
#pragma unroll
                for (int l = k + 1; l < 4; l++) {
                    float cv = ux[k]*ux[l] + uy[k]*uy[l] + uz[k]*uz[l];
                    float t = cv + (1.0f / 3.0f);
                    s += t * t;
                }
            atomicAdd(&g_sumq, 1.0f - 0.375f * s);
            atomicAdd(&g_cntvf, 1);
        }
    }
}

// ---------------------------------------------------------------------------
// kernel 3: normalize -> G_r, T_r, integrand. One block.
// ---------------------------------------------------------------------------
__global__ void k_norm(const float* __restrict__ cell, const float* __restrict__ rbins,
                       int N, int nbins, float* __restrict__ out) {
    int tid = threadIdx.x;
    float meanb = ((float)g_nsi * B_SI + (float)(N - g_nsi) * B_O) / (float)N;

    float c0=cell[0],c1=cell[1],c2=cell[2],c3=cell[3],c4=cell[4],c5=cell[5],c6=cell[6],c7=cell[7],c8=cell[8];
    float det = c0*(c4*c8 - c5*c7) - c1*(c3*c8 - c5*c6) + c2*(c3*c7 - c4*c6);
    float V   = fabsf(det);
    float rho = (float)N / V;

    float r0 = rbins[0];
    float dr = rbins[1] - r0;
    float wnorm = 1.0f / (meanb * meanb);

    for (int k = tid; k < nbins; k += blockDim.x) {
        float r = rbins[k];
        float shell = 4.0f * PI_F * r * r * dr;
        float Gr = (g_hist[k] * wnorm) / ((float)N * rho * shell);
        out[k] = Gr;                                   // G_r
        out[nbins + k] = 4.0f * PI_F * rho * r * Gr;   // T_r
        g_integrand[k] = r * r * (Gr - 1.0f);
    }
}

// ---------------------------------------------------------------------------
// kernel 4: S(Q), one thread per Q, plus q_tet write
// ---------------------------------------------------------------------------
__global__ void k_sq(const float* __restrict__ cell, const float* __restrict__ rbins,
                     const float* __restrict__ qbins,
                     int N, int nbins, int nq, float* __restrict__ out) {
    float c0=cell[0],c4=cell[4],c8=cell[8];
    float c1=cell[1],c2=cell[2],c3=cell[3],c5=cell[5],c6=cell[6],c7=cell[7];
    float det = c0*(c4*c8 - c5*c7) - c1*(c3*c8 - c5*c6) + c2*(c3*c7 - c4*c6);
    float rho = (float)N / fabsf(det);
    float dr  = rbins[1] - rbins[0];

    int iq = blockIdx.x * blockDim.x + threadIdx.x;
    if (iq < nq) {
        float Q = qbins[iq];
        float s = 0.0f;
        for (int k = 0; k < nbins; k++) {
            float r  = rbins[k];
            float qr = Q * r;
            float sc = (qr != 0.0f) ? (sinf(qr) / qr) : 1.0f;
            s += g_integrand[k] * sc;
        }
        out[2 * nbins + iq] = 1.0f + 4.0f * PI_F * rho * dr * s;
    }
    if (iq == 0)
        out[2 * nbins + nq] = g_sumq / fmaxf((float)g_cntvf, 1.0f);
}

// ---------------------------------------------------------------------------
// launch
// ---------------------------------------------------------------------------
extern "C" void kernel_launch(void* const* d_in, const int* in_sizes, int n_in,
                              void* d_out, int out_size) {
    const float* pos     = (const float*)d_in[0];
    const float* cell    = (const float*)d_in[1];
    const float* rbins   = (const float*)d_in[2];
    const float* qbins   = (const float*)d_in[3];
    const int*   species = (const int*)d_in[4];

    int N     = in_sizes[0] / 3;
    int nbins = in_sizes[2];
    int nq    = in_sizes[3];
    float* out = (float*)d_out;

    k_zero<<<1, 1>>>();

    int mx = (N > nbins) ? N : nbins;
    k_prep<<<(mx + 255) / 256, 256>>>(pos, species, N, nbins);

    int half = N / 2;
    int histBlocks = (half + IPB - 1) / IPB;
    k_hist<<<histBlocks, IPB * LPI>>>(cell, rbins, N, nbins);

    int tetBlocks = (N + TET_WARPS - 1) / TET_WARPS;
    k_tet<<<tetBlocks, TET_WARPS * 32>>>(cell, N);

    k_norm<<<1, 256>>>(cell, rbins, N, nbins, out);

    k_sq<<<(nq + 127) / 128, 128>>>(cell, rbins, qbins, N, nbins, nq, out);
}

// round 5
// speedup vs baseline: 1.8470x; 1.2735x over previous
#include <cuda_runtime.h>
#include <math.h>

#define B_SI 4.1491f
#define B_O  5.803f
#define CUTOFF 3.5f
#define PI_F 3.14159265358979323846f

#define MAXN 16384
#define MAXB 1024

#define IPB 8    // atom slots per block in hist kernel (each covers i and N-1-i)
#define LPI 32   // j-lanes per atom slot (per y-slice)
#define JSPLIT 2 // gridDim.y split of the j range

__device__ float4 g_pos[MAXN];       // x, y, z, b (scattering length)
__device__ float4 g_sipos[MAXN];     // compacted Si centers
__device__ float4 g_opos[MAXN];      // compacted O atoms
__device__ float  g_hist[MAXB];
__device__ float  g_integrand[MAXB]; // r^2 (G_r - 1)
__device__ float  g_sumq;
__device__ int    g_cntvf;
__device__ int    g_nsi;
__device__ int    g_no;

// ---------------------------------------------------------------------------
// helpers
// ---------------------------------------------------------------------------
__device__ __forceinline__ void load_cell_inv(const float* __restrict__ cell,
                                              float c[9], float inv[9]) {
#pragma unroll
    for (int k = 0; k < 9; k++) c[k] = cell[k];
    float a00=c[0],a01=c[1],a02=c[2],a10=c[3],a11=c[4],a12=c[5],a20=c[6],a21=c[7],a22=c[8];
    float det = a00*(a11*a22 - a12*a21) - a01*(a10*a22 - a12*a20) + a02*(a10*a21 - a11*a20);
    float id = 1.0f / det;
    inv[0]=(a11*a22-a12*a21)*id; inv[1]=(a02*a21-a01*a22)*id; inv[2]=(a01*a12-a02*a11)*id;
    inv[3]=(a12*a20-a10*a22)*id; inv[4]=(a00*a22-a02*a20)*id; inv[5]=(a02*a10-a00*a12)*id;
    inv[6]=(a10*a21-a11*a20)*id; inv[7]=(a01*a20-a00*a21)*id; inv[8]=(a00*a11-a01*a10)*id;
}

__device__ __forceinline__ bool cell_is_diag(const float c[9]) {
    return c[1]==0.0f && c[2]==0.0f && c[3]==0.0f &&
           c[5]==0.0f && c[6]==0.0f && c[7]==0.0f;
}

__device__ __forceinline__ float3 min_image(float dx, float dy, float dz,
                                            const float c[9], const float inv[9]) {
    float fx = dx*inv[0] + dy*inv[3] + dz*inv[6];
    float fy = dx*inv[1] + dy*inv[4] + dz*inv[7];
    float fz = dx*inv[2] + dy*inv[5] + dz*inv[8];
    fx -= rintf(fx); fy -= rintf(fy); fz -= rintf(fz);
    float ox = fx*c[0] + fy*c[3] + fz*c[6];
    float oy = fx*c[1] + fy*c[4] + fz*c[7];
    float oz = fx*c[2] + fy*c[5] + fz*c[8];
    return make_float3(ox, oy, oz);
}

__device__ __forceinline__ float3 min_image_diag(float dx, float dy, float dz,
                                                 float Lx, float Ly, float Lz,
                                                 float iLx, float iLy, float iLz) {
    float fx = dx * iLx, fy = dy * iLy, fz = dz * iLz;
    fx -= rintf(fx); fy -= rintf(fy); fz -= rintf(fz);
    return make_float3(fx * Lx, fy * Ly, fz * Lz);
}

// ---------------------------------------------------------------------------
// kernel 0a: zero counters
// ---------------------------------------------------------------------------
__global__ void k_zero() { g_nsi = 0; g_no = 0; g_sumq = 0.0f; g_cntvf = 0; }

// ---------------------------------------------------------------------------
// kernel 0b: pack positions + b, compact Si / O lists, zero hist
// ---------------------------------------------------------------------------
__global__ void k_prep(const float* __restrict__ pos, const int* __restrict__ species,
                       int N, int nbins) {
    int i = blockIdx.x * blockDim.x + threadIdx.x;
    if (i < N) {
        int isSi = (species[i] == 0);
        float b = isSi ? B_SI : B_O;
        float4 p4 = make_float4(pos[3*i+0], pos[3*i+1], pos[3*i+2], b);
        g_pos[i] = p4;
        if (isSi) {
            int k = atomicAdd(&g_nsi, 1);
            g_sipos[k] = p4;
        } else {
            int k = atomicAdd(&g_no, 1);
            g_opos[k] = p4;
        }
    }
    if (i < nbins) g_hist[i] = 0.0f;
}

// ---------------------------------------------------------------------------
// kernel 1: weighted pair histogram, i<j symmetry (doubled), CIC binning.
// gridDim.y splits the j range (lane stride LPI*JSPLIT) for 2x occupancy.
// ---------------------------------------------------------------------------
__global__ void k_hist(const float* __restrict__ cell, const float* __restrict__ rbins,
                       int N, int nbins) {
    __shared__ float sh[MAXB];
    int tid = threadIdx.x;
    for (int k = tid; k < nbins; k += blockDim.x) sh[k] = 0.0f;

    float c[9], inv[9];
    load_cell_inv(cell, c, inv);
    bool diag = cell_is_diag(c);
    float Lx=c[0], Ly=c[4], Lz=c[8];
    float iLx=1.0f/Lx, iLy=1.0f/Ly, iLz=1.0f/Lz;

    float r0 = rbins[0];
    float dr = rbins[1] - r0;
    float idr = 1.0f / dr;
    float rmax  = r0 + dr * (float)(nbins - 1);
    float rmax2 = rmax * rmax;
    __syncthreads();

    int slot  = tid / LPI;
    int jlane = blockIdx.y * LPI + (tid % LPI);
    const int JSTRIDE = LPI * JSPLIT;
    int half = N / 2;

#pragma unroll 1
    for (int pass = 0; pass < 2; pass++) {
        int i = blockIdx.x * IPB + slot;
        if (i >= half) break;
        if (pass == 1) i = N - 1 - i;
        float4 p = g_pos[i];
        if (diag) {
            for (int j = i + 1 + jlane; j < N; j += JSTRIDE) {
                float4 q = g_pos[j];
                float3 d = min_image_diag(p.x-q.x, p.y-q.y, p.z-q.z, Lx,Ly,Lz, iLx,iLy,iLz);
                float d2 = d.x*d.x + d.y*d.y + d.z*d.z;
                if (d2 < rmax2) {
                    float dist = sqrtf(d2);
                    float x  = (dist - r0) * idr;
                    float fi = floorf(x);
                    int  i0  = (int)fi;
                    if (i0 >= 0 && i0 < nbins - 1) {
                        float f = x - fi;
                        float w = p.w * q.w;
                        atomicAdd(&sh[i0],     w * (1.0f - f));
                        atomicAdd(&sh[i0 + 1], w * f);
                    }
                }
            }
        } else {
            for (int j = i + 1 + jlane; j < N; j += JSTRIDE) {
                float4 q = g_pos[j];
                float3 d = min_image(p.x-q.x, p.y-q.y, p.z-q.z, c, inv);
                float d2 = d.x*d.x + d.y*d.y + d.z*d.z;
                if (d2 < rmax2) {
                    float dist = sqrtf(d2);
                    float x  = (dist - r0) * idr;
                    float fi = floorf(x);
                    int  i0  = (int)fi;
                    if (i0 >= 0 && i0 < nbins - 1) {
                        float f = x - fi;
                        float w = p.w * q.w;
                        atomicAdd(&sh[i0],     w * (1.0f - f));
                        atomicAdd(&sh[i0 + 1], w * f);
                    }
                }
            }
        }
    }
    __syncthreads();
    for (int k = tid; k < nbins; k += blockDim.x)
        if (sh[k] != 0.0f) atomicAdd(&g_hist[k], 2.0f * sh[k]);   // unordered -> ordered
}

// ---------------------------------------------------------------------------
// kernel 2: tetrahedral order parameter. One WARP per Si center, scanning the
// compacted O list only.
// ---------------------------------------------------------------------------
__global__ void k_tet(const float* __restrict__ cell) {
    int warp = (blockIdx.x * blockDim.x + threadIdx.x) >> 5;
    int lane = threadIdx.x & 31;
    int nsi = g_nsi;
    int no  = g_no;
    if (warp >= nsi) return;

    float c[9], inv[9];
    load_cell_inv(cell, c, inv);
    bool diag = cell_is_diag(c);
    float Lx=c[0], Ly=c[4], Lz=c[8];
    float iLx=1.0f/Lx, iLy=1.0f/Ly, iLz=1.0f/Lz;

    float4 p = g_sipos[warp];

    float bd[4] = {1e12f, 1e12f, 1e12f, 1e12f};   // d^2, ascending
    int   bj[4] = {-1, -1, -1, -1};

    for (int j = lane; j < no; j += 32) {
        float4 q = g_opos[j];
        float3 d = diag ? min_image_diag(p.x-q.x, p.y-q.y, p.z-q.z, Lx,Ly,Lz, iLx,iLy,iLz)
                        : min_image(p.x-q.x, p.y-q.y, p.z-q.z, c, inv);
        float d2 = d.x*d.x + d.y*d.y + d.z*d.z;
        if (d2 < bd[3]) {
            int k = 3;
#pragma unroll
            for (int t = 0; t < 3; t++) {
                if (k > 0 && bd[k-1] > d2) { bd[k] = bd[k-1]; bj[k] = bj[k-1]; k--; }
            }
            bd[k] = d2; bj[k] = j;
        }
    }

    // warp merge of sorted 4-lists
    const unsigned mask = 0xffffffffu;
#pragma unroll
    for (int off = 16; off > 0; off >>= 1) {
        float od[4]; int oj[4];
#pragma unroll
        for (int k = 0; k < 4; k++) {
            od[k] = __shfl_down_sync(mask, bd[k], off);
            oj[k] = __shfl_down_sync(mask, bj[k], off);
        }
        float nd[4]; int nj[4];
        int a = 0, b = 0;
#pragma unroll
        for (int k = 0; k < 4; k++) {
            bool takeA = (b >= 4) || (a < 4 && bd[a] <= od[b]);
            if (takeA) { nd[k] = bd[a]; nj[k] = bj[a]; a++; }
            else       { nd[k] = od[b]; nj[k] = oj[b]; b++; }
        }
#pragma unroll
        for (int k = 0; k < 4; k++) { bd[k] = nd[k]; bj[k] = nj[k]; }
    }

    if (lane == 0) {
        float d3 = sqrtf(bd[3]);
        if (d3 < CUTOFF) {
            float ux[4], uy[4], uz[4];
#pragma unroll
            for (int k = 0; k < 4; k++) {
                float4 q = g_opos[bj[k]];
                float3 d = diag ? min_image_diag(p.x-q.x, p.y-q.y, p.z-q.z, Lx,Ly,Lz, iLx,iLy,iLz)
                                : min_image(p.x-q.x, p.y-q.y, p.z-q.z, c, inv);
                float dk = sqrtf(bd[k]);
                ux[k] = d.x / dk; uy[k] = d.y / dk; uz[k] = d.z / dk;
            }
            float s = 0.0f;
#pragma unroll
            for (int k = 0; k < 4; k++)
#pragma unroll
                for (int l = k + 1; l < 4; l++) {
                    float cv = ux[k]*ux[l] + uy[k]*uy[l] + uz[k]*uz[l];
                    float t = cv + (1.0f / 3.0f);
                    s += t * t;
                }
            atomicAdd(&g_sumq, 1.0f - 0.375f * s);
            atomicAdd(&g_cntvf, 1);
        }
    }
}

// ---------------------------------------------------------------------------
// kernel 3: normalize -> G_r, T_r, integrand. One block.
// ---------------------------------------------------------------------------
__global__ void k_norm(const float* __restrict__ cell, const float* __restrict__ rbins,
                       int N, int nbins, float* __restrict__ out) {
    int tid = threadIdx.x;
    float meanb = ((float)g_nsi * B_SI + (float)(N - g_nsi) * B_O) / (float)N;

    float c0=cell[0],c1=cell[1],c2=cell[2],c3=cell[3],c4=cell[4],c5=cell[5],c6=cell[6],c7=cell[7],c8=cell[8];
    float det = c0*(c4*c8 - c5*c7) - c1*(c3*c8 - c5*c6) + c2*(c3*c7 - c4*c6);
    float V   = fabsf(det);
    float rho = (float)N / V;

    float r0 = rbins[0];
    float dr = rbins[1] - r0;
    float wnorm = 1.0f / (meanb * meanb);

    for (int k = tid; k < nbins; k += blockDim.x) {
        float r = rbins[k];
        float shell = 4.0f * PI_F * r * r * dr;
        float Gr = (g_hist[k] * wnorm) / ((float)N * rho * shell);
        out[k] = Gr;                                   // G_r
        out[nbins + k] = 4.0f * PI_F * rho * r * Gr;   // T_r
        g_integrand[k] = r * r * (Gr - 1.0f);
    }
}

// ---------------------------------------------------------------------------
// kernel 4: S(Q), one thread per Q, plus q_tet write
// ---------------------------------------------------------------------------
__global__ void k_sq(const float* __restrict__ cell, const float* __restrict__ rbins,
                     const float* __restrict__ qbins,
                     int N, int nbins, int nq, float* __restrict__ out) {
    float c0=cell[0],c4=cell[4],c8=cell[8];
    float c1=cell[1],c2=cell[2],c3=cell[3],c5=cell[5],c6=cell[6],c7=cell[7];
    float det = c0*(c4*c8 - c5*c7) - c1*(c3*c8 - c5*c6) + c2*(c3*c7 - c4*c6);
    float rho = (float)N / fabsf(det);
    float dr  = rbins[1] - rbins[0];

    int iq = blockIdx.x * blockDim.x + threadIdx.x;
    if (iq < nq) {
        float Q = qbins[iq];
        float s = 0.0f;
        for (int k = 0; k < nbins; k++) {
            float r  = rbins[k];
            float qr = Q * r;
            float sc = (qr != 0.0f) ? (sinf(qr) / qr) : 1.0f;
            s += g_integrand[k] * sc;
        }
        out[2 * nbins + iq] = 1.0f + 4.0f * PI_F * rho * dr * s;
    }
    if (iq == 0)
        out[2 * nbins + nq] = g_sumq / fmaxf((float)g_cntvf, 1.0f);
}

// ---------------------------------------------------------------------------
// launch
// ---------------------------------------------------------------------------
extern "C" void kernel_launch(void* const* d_in, const int* in_sizes, int n_in,
                              void* d_out, int out_size) {
    const float* pos     = (const float*)d_in[0];
    const float* cell    = (const float*)d_in[1];
    const float* rbins   = (const float*)d_in[2];
    const float* qbins   = (const float*)d_in[3];
    const int*   species = (const int*)d_in[4];

    int N     = in_sizes[0] / 3;
    int nbins = in_sizes[2];
    int nq    = in_sizes[3];
    float* out = (float*)d_out;

    k_zero<<<1, 1>>>();

    int mx = (N > nbins) ? N : nbins;
    k_prep<<<(mx + 255) / 256, 256>>>(pos, species, N, nbins);

    int half = N / 2;
    dim3 hgrid((half + IPB - 1) / IPB, JSPLIT);
    k_hist<<<hgrid, IPB * LPI>>>(cell, rbins, N, nbins);

    // worst case: every atom is a Si center; warps beyond g_nsi exit at once
    int tetBlocks = (N + 7) / 8;                  // 8 warps (256 threads) per block
    k_tet<<<tetBlocks, 256>>>(cell);

    k_norm<<<1, 256>>>(cell, rbins, N, nbins, out);

    k_sq<<<(nq + 127) / 128, 128>>>(cell, rbins, qbins, N, nbins, nq, out);
}

// round 7
// speedup vs baseline: 2.0384x; 1.1036x over previous
#include <cuda_runtime.h>
#include <math.h>

#define B_SI 4.1491f
#define B_O  5.803f
#define CUTOFF 3.5f
#define PI_F 3.14159265358979323846f

#define MAXN 16384
#define MAXB 1024

#define IPB 8    // atom slots per block in hist kernel (each covers i and N-1-i)
#define LPI 32   // j-lanes per atom slot (per y-slice)
#define JSPLIT 4 // gridDim.y split of the j range

__device__ float4 g_pos[MAXN];       // x, y, z, b (scattering length)
__device__ float4 g_sipos[MAXN];     // compacted Si centers
__device__ float4 g_opos[MAXN];      // compacted O atoms
__device__ float  g_hist[MAXB];
__device__ float  g_integrand[MAXB]; // r^2 (G_r - 1)
__device__ float  g_sumq;
__device__ int    g_cntvf;
__device__ int    g_nsi;
__device__ int    g_no;

// ---------------------------------------------------------------------------
// helpers
// ---------------------------------------------------------------------------
__device__ __forceinline__ void load_cell_inv(const float* __restrict__ cell,
                                              float c[9], float inv[9]) {
#pragma unroll
    for (int k = 0; k < 9; k++) c[k] = cell[k];
    float a00=c[0],a01=c[1],a02=c[2],a10=c[3],a11=c[4],a12=c[5],a20=c[6],a21=c[7],a22=c[8];
    float det = a00*(a11*a22 - a12*a21) - a01*(a10*a22 - a12*a20) + a02*(a10*a21 - a11*a20);
    float id = 1.0f / det;
    inv[0]=(a11*a22-a12*a21)*id; inv[1]=(a02*a21-a01*a22)*id; inv[2]=(a01*a12-a02*a11)*id;
    inv[3]=(a12*a20-a10*a22)*id; inv[4]=(a00*a22-a02*a20)*id; inv[5]=(a02*a10-a00*a12)*id;
    inv[6]=(a10*a21-a11*a20)*id; inv[7]=(a01*a20-a00*a21)*id; inv[8]=(a00*a11-a01*a10)*id;
}

__device__ __forceinline__ bool cell_is_diag(const float c[9]) {
    return c[1]==0.0f && c[2]==0.0f && c[3]==0.0f &&
           c[5]==0.0f && c[6]==0.0f && c[7]==0.0f;
}

__device__ __forceinline__ float3 min_image(float dx, float dy, float dz,
                                            const float c[9], const float inv[9]) {
    float fx = dx*inv[0] + dy*inv[3] + dz*inv[6];
    float fy = dx*inv[1] + dy*inv[4] + dz*inv[7];
    float fz = dx*inv[2] + dy*inv[5] + dz*inv[8];
    fx -= rintf(fx); fy -= rintf(fy); fz -= rintf(fz);
    float ox = fx*c[0] + fy*c[3] + fz*c[6];
    float oy = fx*c[1] + fy*c[4] + fz*c[7];
    float oz = fx*c[2] + fy*c[5] + fz*c[8];
    return make_float3(ox, oy, oz);
}

__device__ __forceinline__ float3 min_image_diag(float dx, float dy, float dz,
                                                 float Lx, float Ly, float Lz,
                                                 float iLx, float iLy, float iLz) {
    float fx = dx * iLx, fy = dy * iLy, fz = dz * iLz;
    fx -= rintf(fx); fy -= rintf(fy); fz -= rintf(fz);
    return make_float3(fx * Lx, fy * Ly, fz * Lz);
}

// ---------------------------------------------------------------------------
// kernel 0a: zero counters
// ---------------------------------------------------------------------------
__global__ void k_zero() { g_nsi = 0; g_no = 0; g_sumq = 0.0f; g_cntvf = 0; }

// ---------------------------------------------------------------------------
// kernel 0b: pack positions + b, compact Si / O lists, zero hist
// ---------------------------------------------------------------------------
__global__ void k_prep(const float* __restrict__ pos, const int* __restrict__ species,
                       int N, int nbins) {
    int i = blockIdx.x * blockDim.x + threadIdx.x;
    if (i < N) {
        int isSi = (species[i] == 0);
        float b = isSi ? B_SI : B_O;
        float4 p4 = make_float4(pos[3*i+0], pos[3*i+1], pos[3*i+2], b);
        g_pos[i] = p4;
        if (isSi) {
            int k = atomicAdd(&g_nsi, 1);
            g_sipos[k] = p4;
        } else {
            int k = atomicAdd(&g_no, 1);
            g_opos[k] = p4;
        }
    }
    if (i < nbins) g_hist[i] = 0.0f;
}

// ---------------------------------------------------------------------------
// kernel 1: weighted pair histogram, i<j symmetry (doubled), CIC binning.
// gridDim.y splits the j range for occupancy; manual 2x unroll for MLP.
// ---------------------------------------------------------------------------
__device__ __forceinline__ void hist_pair(float* sh, const float4& p, const float4& q,
                                          float Lx, float Ly, float Lz,
                                          float iLx, float iLy, float iLz,
                                          float r0, float idr, float rmax2, int nbins) {
    float3 d = min_image_diag(p.x-q.x, p.y-q.y, p.z-q.z, Lx,Ly,Lz, iLx,iLy,iLz);
    float d2 = d.x*d.x + d.y*d.y + d.z*d.z;
    if (d2 < rmax2) {
        float dist = sqrtf(d2);
        float x  = (dist - r0) * idr;
        float fi = floorf(x);
        int  i0  = (int)fi;
        if (i0 >= 0 && i0 < nbins - 1) {
            float f = x - fi;
            float w = p.w * q.w;
            atomicAdd(&sh[i0],     w * (1.0f - f));
            atomicAdd(&sh[i0 + 1], w * f);
        }
    }
}

__device__ __forceinline__ void hist_pair_gen(float* sh, const float4& p, const float4& q,
                                              const float c[9], const float inv[9],
                                              float r0, float idr, float rmax2, int nbins) {
    float3 d = min_image(p.x-q.x, p.y-q.y, p.z-q.z, c, inv);
    float d2 = d.x*d.x + d.y*d.y + d.z*d.z;
    if (d2 < rmax2) {
        float dist = sqrtf(d2);
        float x  = (dist - r0) * idr;
        float fi = floorf(x);
        int  i0  = (int)fi;
        if (i0 >= 0 && i0 < nbins - 1) {
            float f = x - fi;
            float w = p.w * q.w;
            atomicAdd(&sh[i0],     w * (1.0f - f));
            atomicAdd(&sh[i0 + 1], w * f);
        }
    }
}

__global__ void k_hist(const float* __restrict__ cell, const float* __restrict__ rbins,
                       int N, int nbins) {
    __shared__ float sh[MAXB];
    int tid = threadIdx.x;
    for (int k = tid; k < nbins; k += blockDim.x) sh[k] = 0.0f;

    float c[9], inv[9];
    load_cell_inv(cell, c, inv);
    bool diag = cell_is_diag(c);
    float Lx=c[0], Ly=c[4], Lz=c[8];
    float iLx=1.0f/Lx, iLy=1.0f/Ly, iLz=1.0f/Lz;

    float r0 = rbins[0];
    float dr = rbins[1] - r0;
    float idr = 1.0f / dr;
    float rmax  = r0 + dr * (float)(nbins - 1);
    float rmax2 = rmax * rmax;
    __syncthreads();

    int slot  = tid / LPI;
    int jlane = blockIdx.y * LPI + (tid % LPI);
    const int JSTRIDE = LPI * JSPLIT;
    int half = N / 2;

#pragma unroll 1
    for (int pass = 0; pass < 2; pass++) {
        int i = blockIdx.x * IPB + slot;
        if (i >= half) break;
        if (pass == 1) i = N - 1 - i;
        float4 p = g_pos[i];
        int j = i + 1 + jlane;
        if (diag) {
            for (; j + JSTRIDE < N; j += 2 * JSTRIDE) {
                float4 q0 = g_pos[j];
                float4 q1 = g_pos[j + JSTRIDE];
                hist_pair(sh, p, q0, Lx,Ly,Lz, iLx,iLy,iLz, r0, idr, rmax2, nbins);
                hist_pair(sh, p, q1, Lx,Ly,Lz, iLx,iLy,iLz, r0, idr, rmax2, nbins);
            }
            if (j < N) {
                float4 q0 = g_pos[j];
                hist_pair(sh, p, q0, Lx,Ly,Lz, iLx,iLy,iLz, r0, idr, rmax2, nbins);
            }
        } else {
            for (; j + JSTRIDE < N; j += 2 * JSTRIDE) {
                float4 q0 = g_pos[j];
                float4 q1 = g_pos[j + JSTRIDE];
                hist_pair_gen(sh, p, q0, c, inv, r0, idr, rmax2, nbins);
                hist_pair_gen(sh, p, q1, c, inv, r0, idr, rmax2, nbins);
            }
            if (j < N) {
                float4 q0 = g_pos[j];
                hist_pair_gen(sh, p, q0, c, inv, r0, idr, rmax2, nbins);
            }
        }
    }
    __syncthreads();
    for (int k = tid; k < nbins; k += blockDim.x)
        if (sh[k] != 0.0f) atomicAdd(&g_hist[k], 2.0f * sh[k]);   // unordered -> ordered
}

// ---------------------------------------------------------------------------
// kernel 2: tetrahedral order parameter. One WARP per Si center over the
// compacted O list. Top-4 kept entirely in scalar registers (no local arrays).
// ---------------------------------------------------------------------------
#define CEX_MIN(da, ja, db, jb)  { bool sw_ = (db) < (da); float td_ = sw_ ? (db) : (da); int tj_ = sw_ ? (jb) : (ja); da = td_; ja = tj_; }
#define CEX_SORT(da, ja, db, jb) { bool sw_ = (db) < (da); float lo_ = sw_ ? (db) : (da); float hi_ = sw_ ? (da) : (db); int lj_ = sw_ ? (jb) : (ja); int hj_ = sw_ ? (ja) : (jb); da = lo_; ja = lj_; db = hi_; jb = hj_; }

__global__ void k_tet(const float* __restrict__ cell) {
    int warp = (blockIdx.x * blockDim.x + threadIdx.x) >> 5;
    int lane = threadIdx.x & 31;
    int nsi = g_nsi;
    int no  = g_no;
    if (warp >= nsi) return;

    float c[9], inv[9];
    load_cell_inv(cell, c, inv);
    bool diag = cell_is_diag(c);
    float Lx=c[0], Ly=c[4], Lz=c[8];
    float iLx=1.0f/Lx, iLy=1.0f/Ly, iLz=1.0f/Lz;

    float4 p = g_sipos[warp];

    // sorted ascending: d0 <= d1 <= d2 <= d3 (squared distances), all registers
    float d0=1e12f, d1=1e12f, d2v=1e12f, d3v=1e12f;
    int   j0=-1, j1=-1, j2=-1, j3=-1;

    for (int j = lane; j < no; j += 32) {
        float4 q = g_opos[j];
        float3 d = diag ? min_image_diag(p.x-q.x, p.y-q.y, p.z-q.z, Lx,Ly,Lz, iLx,iLy,iLz)
                        : min_image(p.x-q.x, p.y-q.y, p.z-q.z, c, inv);
        float dd = d.x*d.x + d.y*d.y + d.z*d.z;
        if (dd < d3v) {
            if (dd < d2v) {
                d3v = d2v; j3 = j2;
                if (dd < d1) {
                    d2v = d1; j2 = j1;
                    if (dd < d0) { d1 = d0; j1 = j0; d0 = dd; j0 = j; }
                    else         { d1 = dd; j1 = j; }
                } else { d2v = dd; j2 = j; }
            } else { d3v = dd; j3 = j; }
        }
    }

    // warp merge of sorted 4-lists: bitonic half-cleaner + 4-sort, registers only
    const unsigned mask = 0xffffffffu;
#pragma unroll
    for (int off = 16; off > 0; off >>= 1) {
        float od0 = __shfl_down_sync(mask, d0,  off);
        float od1 = __shfl_down_sync(mask, d1,  off);
        float od2 = __shfl_down_sync(mask, d2v, off);
        float od3 = __shfl_down_sync(mask, d3v, off);
        int   oj0 = __shfl_down_sync(mask, j0,  off);
        int   oj1 = __shfl_down_sync(mask, j1,  off);
        int   oj2 = __shfl_down_sync(mask, j2,  off);
        int   oj3 = __shfl_down_sync(mask, j3,  off);
        // half-cleaner: a_i vs b_{3-i}, keep min -> lowest 4 of the union (bitonic)
        CEX_MIN(d0,  j0, od3, oj3);
        CEX_MIN(d1,  j1, od2, oj2);
        CEX_MIN(d2v, j2, od1, oj1);
        CEX_MIN(d3v, j3, od0, oj0);
        // bitonic sort of 4
        CEX_SORT(d0,  j0, d2v, j2);
        CEX_SORT(d1,  j1, d3v, j3);
        CEX_SORT(d0,  j0, d1,  j1);
        CEX_SORT(d2v, j2, d3v, j3);
    }

    if (lane == 0) {
        float dist3 = sqrtf(d3v);
        if (dist3 < CUTOFF) {
            float ux[4], uy[4], uz[4];
            float dsq[4] = {d0, d1, d2v, d3v};
            int   jj[4]  = {j0, j1, j2, j3};
#pragma unroll
            for (int k = 0; k < 4; k++) {
                float4 q = g_opos[jj[k]];
                float3 d = diag ? min_image_diag(p.x-q.x, p.y-q.y, p.z-q.z, Lx,Ly,Lz, iLx,iLy,iLz)
                                : min_image(p.x-q.x, p.y-q.y, p.z-q.z, c, inv);
                float dk = sqrtf(dsq[k]);
                ux[k] = d.x / dk; uy[k] = d.y / dk; uz[k] = d.z / dk;
            }
            float s = 0.0f;
#pragma unroll
            for (int k = 0; k < 4; k++)
#pragma unroll
                for (int l = k + 1; l < 4; l++) {
                    float cv = ux[k]*ux[l] + uy[k]*uy[l] + uz[k]*uz[l];
                    float t = cv + (1.0f / 3.0f);
                    s += t * t;
                }
            atomicAdd(&g_sumq, 1.0f - 0.375f * s);
            atomicAdd(&g_cntvf, 1);
        }
    }
}

// ---------------------------------------------------------------------------
// kernel 3: normalize -> G_r, T_r, integrand. One block.
// ---------------------------------------------------------------------------
__global__ void k_norm(const float* __restrict__ cell, const float* __restrict__ rbins,
                       int N, int nbins, float* __restrict__ out) {
    int tid = threadIdx.x;
    float meanb = ((float)g_nsi * B_SI + (float)(N - g_nsi) * B_O) / (float)N;

    float c0=cell[0],c1=cell[1],c2=cell[2],c3=cell[3],c4=cell[4],c5=cell[5],c6=cell[6],c7=cell[7],c8=cell[8];
    float det = c0*(c4*c8 - c5*c7) - c1*(c3*c8 - c5*c6) + c2*(c3*c7 - c4*c6);
    float V   = fabsf(det);
    float rho = (float)N / V;

    float r0 = rbins[0];
    float dr = rbins[1] - r0;
    float wnorm = 1.0f / (meanb * meanb);

    for (int k = tid; k < nbins; k += blockDim.x) {
        float r = rbins[k];
        float shell = 4.0f * PI_F * r * r * dr;
        float Gr = (g_hist[k] * wnorm) / ((float)N * rho * shell);
        out[k] = Gr;                                   // G_r
        out[nbins + k] = 4.0f * PI_F * rho * r * Gr;   // T_r
        g_integrand[k] = r * r * (Gr - 1.0f);
    }
}

// ---------------------------------------------------------------------------
// kernel 4: S(Q), one thread per Q, plus q_tet write
// ---------------------------------------------------------------------------
__global__ void k_sq(const float* __restrict__ cell, const float* __restrict__ rbins,
                     const float* __restrict__ qbins,
                     int N, int nbins, int nq, float* __restrict__ out) {
    float c0=cell[0],c4=cell[4],c8=cell[8];
    float c1=cell[1],c2=cell[2],c3=cell[3],c5=cell[5],c6=cell[6],c7=cell[7];
    float det = c0*(c4*c8 - c5*c7) - c1*(c3*c8 - c5*c6) + c2*(c3*c7 - c4*c6);
    float rho = (float)N / fabsf(det);
    float dr  = rbins[1] - rbins[0];

    int iq = blockIdx.x * blockDim.x + threadIdx.x;
    if (iq < nq) {
        float Q = qbins[iq];
        float s = 0.0f;
        for (int k = 0; k < nbins; k++) {
            float r  = rbins[k];
            float qr = Q * r;
            float sc = (qr != 0.0f) ? (sinf(qr) / qr) : 1.0f;
            s += g_integrand[k] * sc;
        }
        out[2 * nbins + iq] = 1.0f + 4.0f * PI_F * rho * dr * s;
    }
    if (iq == 0)
        out[2 * nbins + nq] = g_sumq / fmaxf((float)g_cntvf, 1.0f);
}

// ---------------------------------------------------------------------------
// launch
// ---------------------------------------------------------------------------
extern "C" void kernel_launch(void* const* d_in, const int* in_sizes, int n_in,
                              void* d_out, int out_size) {
    const float* pos     = (const float*)d_in[0];
    const float* cell    = (const float*)d_in[1];
    const float* rbins   = (const float*)d_in[2];
    const float* qbins   = (const float*)d_in[3];
    const int*   species = (const int*)d_in[4];

    int N     = in_sizes[0] / 3;
    int nbins = in_sizes[2];
    int nq    = in_sizes[3];
    float* out = (float*)d_out;

    k_zero<<<1, 1>>>();

    int mx = (N > nbins) ? N : nbins;
    k_prep<<<(mx + 255) / 256, 256>>>(pos, species, N, nbins);

    int half = N / 2;
    dim3 hgrid((half + IPB - 1) / IPB, JSPLIT);
    k_hist<<<hgrid, IPB * LPI>>>(cell, rbins, N, nbins);

    // worst case: every atom is a Si center; warps beyond g_nsi exit at once
    int tetBlocks = (N + 7) / 8;                  // 8 warps (256 threads) per block
    k_tet<<<tetBlocks, 256>>>(cell);

    k_norm<<<1, 256>>>(cell, rbins, N, nbins, out);

    k_sq<<<(nq + 127) / 128, 128>>>(cell, rbins, qbins, N, nbins, nq, out);
}